// round 3
// baseline (speedup 1.0000x reference)
#include <cuda_runtime.h>
#include <cstdint>

// ---------------------------------------------------------------------------
// Paillier decryption, CRT-factored via tiny lookup tables.
//
//   n = 3599 = 59*61, n^2 = 12,952,801 = 3481 * 3721 (= p^2 * q^2, coprime)
//   lambda = lcm(58,60) = 1740, mu = 1740^{-1} mod 3599 = 1119
//   r = c^1740 mod n^2 via CRT:  r_p = (c mod 3481)^1740 mod 3481,
//   r_q likewise mod 3721; Garner: t=(r_q-r_p)*inv(3481) mod 3721 (inv=1876),
//   r = r_p + 3481*t.
//   m = (floor((r-1)/n) * mu) mod n = (((r + n^2 - 1)/n) * mu) mod n
//   out = relu( float(m) * (inv_scale / 1000) )
//
// All ciphertext values < 2^24, so the harness may deliver them losslessly as
// int64, int32, float32 or double. A 1-thread probe kernel classifies the
// buffer layout from its bit patterns; the hot kernel branches uniformly.
// ---------------------------------------------------------------------------

#define P2 3481u
#define Q2 3721u
#define NN 3599u
#define N2 12952801u
#define MU 1119u
#define LAMBDA 1740u
#define INV_P2_MOD_Q2 1876u

__device__ uint32_t g_Ptab[3481];
__device__ uint32_t g_Atab[3721];
__device__ int g_mode;   // 0=int64, 1=int32, 2=float32, 3=double

__device__ __forceinline__ uint32_t powmod_lambda(uint32_t b, uint32_t mod) {
    uint32_t r = 1u;
    uint32_t e = LAMBDA;               // 1740 = 0b11011001100, 11 bits
    b %= mod;
    #pragma unroll
    for (int i = 0; i < 11; i++) {
        if (e & 1u) r = (r * b) % mod;
        b = (b * b) % mod;
        e >>= 1u;
    }
    return r;
}

__global__ void init_tables_kernel() {
    int i = blockIdx.x * blockDim.x + threadIdx.x;
    if (i < 3481) {
        uint32_t rp = powmod_lambda((uint32_t)i, P2);
        uint32_t bq = (Q2 - (rp * INV_P2_MOD_Q2) % Q2) % Q2;
        g_Ptab[i] = rp | (bq << 16);
    } else if (i < 3481 + 3721) {
        uint32_t y  = (uint32_t)(i - 3481);
        uint32_t aq = (powmod_lambda(y, Q2) * INV_P2_MOD_Q2) % Q2;
        g_Atab[y] = aq;
    }
}

__global__ void probe_layout_kernel(const uint32_t* __restrict__ w) {
    // Deterministic classification of the input buffer's element layout.
    bool odd_zero   = true;   // int64: high halves are 0 (values < 2^32)
    bool all_small  = true;   // int32: every word < 2^24
    bool dbl_exp    = true;   // double: hi-word exponent in [0x3FF,0x416]
    bool even_low29 = true;   // double: integer<2^24 -> mantissa low 29 bits 0
    #pragma unroll
    for (int i = 0; i < 64; i++) {
        uint32_t v = w[i];
        if (i & 1) {
            if (v != 0u) odd_zero = false;
            uint32_t e = (v >> 20) & 0x7FFu;
            if (e < 0x3FFu || e > 0x416u) dbl_exp = false;
        } else {
            if (v & 0x1FFFFFFFu) even_low29 = false;
        }
        if (v >= 0x01000000u) all_small = false;
    }
    int mode;
    if (odd_zero)                  mode = 0;   // int64
    else if (all_small)            mode = 1;   // int32
    else if (dbl_exp && even_low29) mode = 3;  // double
    else                           mode = 2;   // float32
    g_mode = mode;
}

__device__ __forceinline__ float dec_one(uint32_t cv, const uint32_t* sP,
                                         const uint32_t* sA, float s) {
    uint32_t xp = cv % P2;
    uint32_t yq = cv % Q2;
    uint32_t pw = sP[xp];
    uint32_t a  = sA[yq];
    uint32_t rp = pw & 0xFFFFu;
    uint32_t t  = a + (pw >> 16);
    if (t >= Q2) t -= Q2;
    uint32_t r = rp + P2 * t;          // r = c^lambda mod n^2, < n^2
    uint32_t u = r + (N2 - 1u);        // < 2 n^2 < 2^25
    uint32_t q = u / NN;               // = floor((r-1)/n) + n
    uint32_t m = (q * MU) % NN;        // q*MU < 7198*1119 < 2^32
    return fmaxf((float)m * s, 0.0f);
}

__device__ __forceinline__ uint32_t load_cv(const void* in, long long i, int mode) {
    switch (mode) {
        case 0:  return (uint32_t)((const unsigned long long*)in)[i];
        case 1:  return ((const uint32_t*)in)[i];
        case 2:  return (uint32_t)((const float*)in)[i];
        default: return (uint32_t)((const double*)in)[i];
    }
}

__global__ __launch_bounds__(256) void paillier_dec_kernel(
    const void* __restrict__ in,
    const float* __restrict__ inv_scale,
    float* __restrict__ out,
    long long n)
{
    __shared__ uint32_t sP[3481];
    __shared__ uint32_t sA[3721];
    for (int i = threadIdx.x; i < 3481; i += 256) sP[i] = g_Ptab[i];
    for (int i = threadIdx.x; i < 3721; i += 256) sA[i] = g_Atab[i];
    __syncthreads();

    const int mode = g_mode;           // uniform across the grid
    const float s = inv_scale[0] / 1000.0f;

    long long base = ((long long)blockIdx.x * 256 + threadIdx.x) * 4;
    if (base + 4 <= n) {
        uint32_t cv0, cv1, cv2, cv3;
        if (mode == 1) {               // int32: one 16B load
            uint4 v = ((const uint4*)in)[base >> 2];
            cv0 = v.x; cv1 = v.y; cv2 = v.z; cv3 = v.w;
        } else if (mode == 2) {        // float32: one 16B load
            float4 v = ((const float4*)in)[base >> 2];
            cv0 = (uint32_t)v.x; cv1 = (uint32_t)v.y;
            cv2 = (uint32_t)v.z; cv3 = (uint32_t)v.w;
        } else if (mode == 0) {        // int64: two 16B loads, take low words
            const ulonglong2* cp = (const ulonglong2*)in + (base >> 1);
            ulonglong2 a = cp[0], b = cp[1];
            cv0 = (uint32_t)a.x; cv1 = (uint32_t)a.y;
            cv2 = (uint32_t)b.x; cv3 = (uint32_t)b.y;
        } else {                       // double: two 16B loads
            const double2* cp = (const double2*)in + (base >> 1);
            double2 a = cp[0], b = cp[1];
            cv0 = (uint32_t)a.x; cv1 = (uint32_t)a.y;
            cv2 = (uint32_t)b.x; cv3 = (uint32_t)b.y;
        }
        float4 o;
        o.x = dec_one(cv0, sP, sA, s);
        o.y = dec_one(cv1, sP, sA, s);
        o.z = dec_one(cv2, sP, sA, s);
        o.w = dec_one(cv3, sP, sA, s);
        *reinterpret_cast<float4*>(out + base) = o;
    } else {
        for (long long i = base; i < n; i++)
            out[i] = dec_one(load_cv(in, i, mode), sP, sA, s);
    }
}

extern "C" void kernel_launch(void* const* d_in, const int* in_sizes, int n_in,
                              void* d_out, int out_size) {
    // Identify inputs by size: ciphertext tensor is huge, inv_scale is 1 elem.
    int ci = 0, si = 1;
    if (n_in >= 2 && in_sizes[0] <= 1) { ci = 1; si = 0; }
    const void* c        = d_in[ci];
    const float* inv_scl = (const float*)d_in[si];
    float* out           = (float*)d_out;
    long long n = out_size;            // output element count is unambiguous

    init_tables_kernel<<<(3481 + 3721 + 255) / 256, 256>>>();
    probe_layout_kernel<<<1, 1>>>((const uint32_t*)c);

    const int threads = 256;
    const long long per_blk = threads * 4;
    int blocks = (int)((n + per_blk - 1) / per_blk);
    paillier_dec_kernel<<<blocks, threads>>>(c, inv_scl, out, n);
}

// round 4
// speedup vs baseline: 2.5437x; 2.5437x over previous
#include <cuda_runtime.h>
#include <cstdint>

// ---------------------------------------------------------------------------
// Paillier decryption, CRT-factored via tiny lookup tables.
//
//   n = 3599 = 59*61, n^2 = 12,952,801 = 3481 * 3721 (= p^2 * q^2, coprime)
//   lambda = lcm(58,60) = 1740, mu = 1740^{-1} mod 3599 = 1119
//   r = c^1740 mod n^2 via CRT:  r_p = (c mod 3481)^1740 mod 3481,
//   r_q likewise mod 3721; Garner: t=(r_q-r_p)*inv(3481) mod 3721 (inv=1876),
//   r = r_p + 3481*t.
//   m = (floor((r-1)/n) * mu) mod n = (((r + n^2 - 1)/n) * mu) mod n
//   out = relu( float(m) * (inv_scale / 1000) )
//
// R4: persistent grid-stride blocks (1184 = 148 SMs x 8). R3 launched 32768
// short-lived blocks, each staging 28.8KB of tables -> 944MB of L2 traffic
// dwarfing the 400MB of real I/O. Now staging is 1184 x 21KB ~= 25MB.
// Atab packed to uint16 (values < 3721).
// ---------------------------------------------------------------------------

#define P2 3481u
#define Q2 3721u
#define NN 3599u
#define N2 12952801u
#define MU 1119u
#define LAMBDA 1740u
#define INV_P2_MOD_Q2 1876u

__device__ uint32_t g_Ptab[3481];
__device__ uint16_t g_Atab[3721];
__device__ int g_mode;   // 0=int64, 1=int32, 2=float32, 3=double

__device__ __forceinline__ uint32_t powmod_lambda(uint32_t b, uint32_t mod) {
    uint32_t r = 1u;
    uint32_t e = LAMBDA;               // 1740 = 0b11011001100, 11 bits
    b %= mod;
    #pragma unroll
    for (int i = 0; i < 11; i++) {
        if (e & 1u) r = (r * b) % mod;
        b = (b * b) % mod;
        e >>= 1u;
    }
    return r;
}

__global__ void init_tables_kernel() {
    int i = blockIdx.x * blockDim.x + threadIdx.x;
    if (i < 3481) {
        uint32_t rp = powmod_lambda((uint32_t)i, P2);
        uint32_t bq = (Q2 - (rp * INV_P2_MOD_Q2) % Q2) % Q2;
        g_Ptab[i] = rp | (bq << 16);
    } else if (i < 3481 + 3721) {
        uint32_t y  = (uint32_t)(i - 3481);
        uint32_t aq = (powmod_lambda(y, Q2) * INV_P2_MOD_Q2) % Q2;
        g_Atab[y] = (uint16_t)aq;
    }
}

__global__ void probe_layout_kernel(const uint32_t* __restrict__ w) {
    // Deterministic classification of the input buffer's element layout.
    bool odd_zero   = true;   // int64: high halves are 0 (values < 2^32)
    bool all_small  = true;   // int32: every word < 2^24
    bool dbl_exp    = true;   // double: hi-word exponent in [0x3FF,0x416]
    bool even_low29 = true;   // double: integer<2^24 -> mantissa low 29 bits 0
    #pragma unroll
    for (int i = 0; i < 64; i++) {
        uint32_t v = w[i];
        if (i & 1) {
            if (v != 0u) odd_zero = false;
            uint32_t e = (v >> 20) & 0x7FFu;
            if (e < 0x3FFu || e > 0x416u) dbl_exp = false;
        } else {
            if (v & 0x1FFFFFFFu) even_low29 = false;
        }
        if (v >= 0x01000000u) all_small = false;
    }
    int mode;
    if (odd_zero)                   mode = 0;   // int64
    else if (all_small)             mode = 1;   // int32
    else if (dbl_exp && even_low29) mode = 3;   // double
    else                            mode = 2;   // float32
    g_mode = mode;
}

__device__ __forceinline__ float dec_one(uint32_t cv, const uint32_t* sP,
                                         const uint16_t* sA, float s) {
    uint32_t xp = cv % P2;
    uint32_t yq = cv % Q2;
    uint32_t pw = sP[xp];
    uint32_t a  = (uint32_t)sA[yq];
    uint32_t rp = pw & 0xFFFFu;
    uint32_t t  = a + (pw >> 16);
    if (t >= Q2) t -= Q2;
    uint32_t r = rp + P2 * t;          // r = c^lambda mod n^2, < n^2
    uint32_t u = r + (N2 - 1u);        // < 2 n^2 < 2^25
    uint32_t q = u / NN;               // = floor((r-1)/n) + n
    uint32_t m = (q * MU) % NN;        // q*MU < 7198*1119 < 2^32
    return fmaxf((float)m * s, 0.0f);
}

__global__ __launch_bounds__(256) void paillier_dec_kernel(
    const void* __restrict__ in,
    const float* __restrict__ inv_scale,
    float* __restrict__ out,
    long long n)
{
    __shared__ uint32_t sP[3481];
    __shared__ uint16_t sA[3721];
    for (int i = threadIdx.x; i < 3481; i += 256) sP[i] = g_Ptab[i];
    for (int i = threadIdx.x; i < 3721; i += 256) sA[i] = g_Atab[i];
    __syncthreads();

    const int mode = g_mode;           // uniform across the grid
    const float s = inv_scale[0] / 1000.0f;

    const long long nquads = n >> 2;
    const long long qstride = (long long)gridDim.x * blockDim.x;

    for (long long q = (long long)blockIdx.x * blockDim.x + threadIdx.x;
         q < nquads; q += qstride) {
        uint32_t cv0, cv1, cv2, cv3;
        if (mode == 1) {               // int32: one 16B load
            uint4 v = ((const uint4*)in)[q];
            cv0 = v.x; cv1 = v.y; cv2 = v.z; cv3 = v.w;
        } else if (mode == 2) {        // float32: one 16B load
            float4 v = ((const float4*)in)[q];
            cv0 = (uint32_t)v.x; cv1 = (uint32_t)v.y;
            cv2 = (uint32_t)v.z; cv3 = (uint32_t)v.w;
        } else if (mode == 0) {        // int64: two 16B loads, take low words
            const ulonglong2* cp = (const ulonglong2*)in + (q << 1);
            ulonglong2 a = cp[0], b = cp[1];
            cv0 = (uint32_t)a.x; cv1 = (uint32_t)a.y;
            cv2 = (uint32_t)b.x; cv3 = (uint32_t)b.y;
        } else {                       // double: two 16B loads
            const double2* cp = (const double2*)in + (q << 1);
            double2 a = cp[0], b = cp[1];
            cv0 = (uint32_t)a.x; cv1 = (uint32_t)a.y;
            cv2 = (uint32_t)b.x; cv3 = (uint32_t)b.y;
        }
        float4 o;
        o.x = dec_one(cv0, sP, sA, s);
        o.y = dec_one(cv1, sP, sA, s);
        o.z = dec_one(cv2, sP, sA, s);
        o.w = dec_one(cv3, sP, sA, s);
        ((float4*)out)[q] = o;
    }

    // Scalar tail (n not divisible by 4): handled by the first few threads.
    long long tail = nquads << 2;
    long long ti = tail + (long long)blockIdx.x * blockDim.x + threadIdx.x;
    if (blockIdx.x == 0 && ti < n) {
        uint32_t cv;
        switch (mode) {
            case 0:  cv = (uint32_t)((const unsigned long long*)in)[ti]; break;
            case 1:  cv = ((const uint32_t*)in)[ti]; break;
            case 2:  cv = (uint32_t)((const float*)in)[ti]; break;
            default: cv = (uint32_t)((const double*)in)[ti]; break;
        }
        out[ti] = dec_one(cv, sP, sA, s);
    }
}

extern "C" void kernel_launch(void* const* d_in, const int* in_sizes, int n_in,
                              void* d_out, int out_size) {
    // Identify inputs by size: ciphertext tensor is huge, inv_scale is 1 elem.
    int ci = 0, si = 1;
    if (n_in >= 2 && in_sizes[0] <= 1) { ci = 1; si = 0; }
    const void* c        = d_in[ci];
    const float* inv_scl = (const float*)d_in[si];
    float* out           = (float*)d_out;
    long long n = out_size;            // output element count is unambiguous

    init_tables_kernel<<<(3481 + 3721 + 255) / 256, 256>>>();
    probe_layout_kernel<<<1, 1>>>((const uint32_t*)c);

    // Persistent blocks: 148 SMs x 8 blocks (256 thr each = 64 warps/SM).
    int blocks = 148 * 8;
    paillier_dec_kernel<<<blocks, 256>>>(c, inv_scl, out, n);
}

// round 5
// speedup vs baseline: 3.5592x; 1.3992x over previous
#include <cuda_runtime.h>
#include <cstdint>

// ---------------------------------------------------------------------------
// Paillier decryption, CRT-factored via tiny lookup tables.
//
//   n = 3599 = 59*61, n^2 = 12,952,801 = 3481 * 3721 (= p^2 * q^2, coprime)
//   lambda = lcm(58,60) = 1740, mu = 1740^{-1} mod 3599 = 1119
//   r = c^1740 mod n^2 via CRT:  r_p = (c mod 3481)^1740 mod 3481,
//   r_q likewise mod 3721; Garner: t=(r_q-r_p)*inv(3481) mod 3721 (inv=1876),
//   r = r_p + 3481*t.
//   m = (floor((r-1)/n) * mu) mod n = (((r + n^2 - 1)/n) * mu) mod n
//   out = relu( float(m) * (inv_scale / 1000) )
//
// R5: single setup kernel (tables + layout probe) so ncu samples the hot
// kernel; mode-templated grid-stride loop (no per-iter branch); 8 elems per
// thread per iteration; streaming cache hints on the bulk I/O.
// ---------------------------------------------------------------------------

#define P2 3481u
#define Q2 3721u
#define NN 3599u
#define N2 12952801u
#define MU 1119u
#define LAMBDA 1740u
#define INV_P2_MOD_Q2 1876u

__device__ uint32_t g_Ptab[3481];
__device__ uint16_t g_Atab[3721];
__device__ int g_mode;   // 0=int64, 1=int32, 2=float32, 3=double

__device__ __forceinline__ uint32_t powmod_lambda(uint32_t b, uint32_t mod) {
    uint32_t r = 1u;
    uint32_t e = LAMBDA;               // 1740 = 0b11011001100, 11 bits
    b %= mod;
    #pragma unroll
    for (int i = 0; i < 11; i++) {
        if (e & 1u) r = (r * b) % mod;
        b = (b * b) % mod;
        e >>= 1u;
    }
    return r;
}

__global__ void setup_kernel(const uint32_t* __restrict__ w) {
    int i = blockIdx.x * blockDim.x + threadIdx.x;
    if (i < 3481) {
        uint32_t rp = powmod_lambda((uint32_t)i, P2);
        uint32_t bq = (Q2 - (rp * INV_P2_MOD_Q2) % Q2) % Q2;
        g_Ptab[i] = rp | (bq << 16);
    } else if (i < 3481 + 3721) {
        uint32_t y  = (uint32_t)(i - 3481);
        uint32_t aq = (powmod_lambda(y, Q2) * INV_P2_MOD_Q2) % Q2;
        g_Atab[y] = (uint16_t)aq;
    } else if (i == 3481 + 3721) {
        // Layout probe: classify the input buffer's element encoding.
        bool odd_zero   = true;   // int64: high halves all 0
        bool all_small  = true;   // int32: every word < 2^24
        bool dbl_exp    = true;   // double: hi-word exponent in [0x3FF,0x416]
        bool even_low29 = true;   // double: integer<2^24 -> low 29 bits clear
        #pragma unroll
        for (int k = 0; k < 64; k++) {
            uint32_t v = w[k];
            if (k & 1) {
                if (v != 0u) odd_zero = false;
                uint32_t e = (v >> 20) & 0x7FFu;
                if (e < 0x3FFu || e > 0x416u) dbl_exp = false;
            } else {
                if (v & 0x1FFFFFFFu) even_low29 = false;
            }
            if (v >= 0x01000000u) all_small = false;
        }
        int mode;
        if (odd_zero)                   mode = 0;   // int64
        else if (all_small)             mode = 1;   // int32
        else if (dbl_exp && even_low29) mode = 3;   // double
        else                            mode = 2;   // float32
        g_mode = mode;
    }
}

__device__ __forceinline__ float dec_one(uint32_t cv, const uint32_t* sP,
                                         const uint16_t* sA, float s) {
    uint32_t xp = cv % P2;
    uint32_t yq = cv % Q2;
    uint32_t pw = sP[xp];
    uint32_t a  = (uint32_t)sA[yq];
    uint32_t rp = pw & 0xFFFFu;
    uint32_t t  = a + (pw >> 16);
    if (t >= Q2) t -= Q2;
    uint32_t r = rp + P2 * t;          // r = c^lambda mod n^2, < n^2
    uint32_t u = r + (N2 - 1u);        // < 2 n^2 < 2^25
    uint32_t q = u / NN;               // = floor((r-1)/n) + n
    uint32_t m = (q * MU) % NN;        // q*MU < 7198*1119 < 2^32
    return fmaxf((float)m * s, 0.0f);
}

// Load 8 consecutive elements starting at element offset o (o multiple of 8).
template <int MODE>
__device__ __forceinline__ void load8(const void* in, long long o, uint32_t cv[8]) {
    if (MODE == 1) {
        uint4 a = __ldcs((const uint4*)in + (o >> 2));
        uint4 b = __ldcs((const uint4*)in + (o >> 2) + 1);
        cv[0]=a.x; cv[1]=a.y; cv[2]=a.z; cv[3]=a.w;
        cv[4]=b.x; cv[5]=b.y; cv[6]=b.z; cv[7]=b.w;
    } else if (MODE == 2) {
        float4 a = __ldcs((const float4*)in + (o >> 2));
        float4 b = __ldcs((const float4*)in + (o >> 2) + 1);
        cv[0]=(uint32_t)a.x; cv[1]=(uint32_t)a.y; cv[2]=(uint32_t)a.z; cv[3]=(uint32_t)a.w;
        cv[4]=(uint32_t)b.x; cv[5]=(uint32_t)b.y; cv[6]=(uint32_t)b.z; cv[7]=(uint32_t)b.w;
    } else if (MODE == 0) {
        const ulonglong2* p = (const ulonglong2*)in + (o >> 1);
        ulonglong2 a = __ldcs(p), b = __ldcs(p+1), c = __ldcs(p+2), d = __ldcs(p+3);
        cv[0]=(uint32_t)a.x; cv[1]=(uint32_t)a.y; cv[2]=(uint32_t)b.x; cv[3]=(uint32_t)b.y;
        cv[4]=(uint32_t)c.x; cv[5]=(uint32_t)c.y; cv[6]=(uint32_t)d.x; cv[7]=(uint32_t)d.y;
    } else {
        const double2* p = (const double2*)in + (o >> 1);
        double2 a = __ldcs(p), b = __ldcs(p+1), c = __ldcs(p+2), d = __ldcs(p+3);
        // integer-valued doubles < 2^24: add 2^52, take low mantissa word
        cv[0]=(uint32_t)__double2ll_rn(a.x); cv[1]=(uint32_t)__double2ll_rn(a.y);
        cv[2]=(uint32_t)__double2ll_rn(b.x); cv[3]=(uint32_t)__double2ll_rn(b.y);
        cv[4]=(uint32_t)__double2ll_rn(c.x); cv[5]=(uint32_t)__double2ll_rn(c.y);
        cv[6]=(uint32_t)__double2ll_rn(d.x); cv[7]=(uint32_t)__double2ll_rn(d.y);
    }
}

template <int MODE>
__device__ __forceinline__ void run_loop(const void* in, float* out, long long n,
                                         const uint32_t* sP, const uint16_t* sA,
                                         float s) {
    const long long nocts  = n >> 3;                      // groups of 8
    const long long stride = (long long)gridDim.x * blockDim.x;
    for (long long g = (long long)blockIdx.x * blockDim.x + threadIdx.x;
         g < nocts; g += stride) {
        long long o = g << 3;
        uint32_t cv[8];
        load8<MODE>(in, o, cv);
        float4 lo, hi;
        lo.x = dec_one(cv[0], sP, sA, s);
        lo.y = dec_one(cv[1], sP, sA, s);
        lo.z = dec_one(cv[2], sP, sA, s);
        lo.w = dec_one(cv[3], sP, sA, s);
        hi.x = dec_one(cv[4], sP, sA, s);
        hi.y = dec_one(cv[5], sP, sA, s);
        hi.z = dec_one(cv[6], sP, sA, s);
        hi.w = dec_one(cv[7], sP, sA, s);
        __stcs((float4*)out + (o >> 2),     lo);
        __stcs((float4*)out + (o >> 2) + 1, hi);
    }
    // Scalar tail (n % 8 != 0)
    long long tail = nocts << 3;
    long long ti = tail + (long long)blockIdx.x * blockDim.x + threadIdx.x;
    if (blockIdx.x == 0 && ti < n) {
        uint32_t cv;
        if (MODE == 0)      cv = (uint32_t)((const unsigned long long*)in)[ti];
        else if (MODE == 1) cv = ((const uint32_t*)in)[ti];
        else if (MODE == 2) cv = (uint32_t)((const float*)in)[ti];
        else                cv = (uint32_t)((const double*)in)[ti];
        out[ti] = dec_one(cv, sP, sA, s);
    }
}

__global__ __launch_bounds__(256) void paillier_dec_kernel(
    const void* __restrict__ in,
    const float* __restrict__ inv_scale,
    float* __restrict__ out,
    long long n)
{
    __shared__ uint32_t sP[3481];
    __shared__ uint16_t sA[3721];
    for (int i = threadIdx.x; i < 3481; i += 256) sP[i] = g_Ptab[i];
    for (int i = threadIdx.x; i < 3721; i += 256) sA[i] = g_Atab[i];
    __syncthreads();

    const float s = inv_scale[0] / 1000.0f;
    switch (g_mode) {                   // uniform; dispatch once
        case 0: run_loop<0>(in, out, n, sP, sA, s); break;
        case 1: run_loop<1>(in, out, n, sP, sA, s); break;
        case 2: run_loop<2>(in, out, n, sP, sA, s); break;
        default: run_loop<3>(in, out, n, sP, sA, s); break;
    }
}

extern "C" void kernel_launch(void* const* d_in, const int* in_sizes, int n_in,
                              void* d_out, int out_size) {
    // Identify inputs by size: ciphertext tensor is huge, inv_scale is 1 elem.
    int ci = 0, si = 1;
    if (n_in >= 2 && in_sizes[0] <= 1) { ci = 1; si = 0; }
    const void* c        = d_in[ci];
    const float* inv_scl = (const float*)d_in[si];
    float* out           = (float*)d_out;
    long long n = out_size;            // output element count is unambiguous

    setup_kernel<<<(3481 + 3721 + 1 + 255) / 256, 256>>>((const uint32_t*)c);

    // Persistent blocks: 148 SMs x 8 blocks (256 thr each = 64 warps/SM).
    paillier_dec_kernel<<<148 * 8, 256>>>(c, inv_scl, out, n);
}